// round 1
// baseline (speedup 1.0000x reference)
#include <cuda_runtime.h>
#include <math.h>

// Problem constants
#define LEVEL   16
#define LENGTH  64
#define TOPK    2
#define SIZE    512
#define BATCH   32
#define NEG     (-1e8f)

#define LPOS    48              // LENGTH - LEVEL
#define NCELLS  904
#define NIDX    768             // LPOS * LEVEL
#define ROWS1   49152           // K*B*LPOS*LEVEL  (GEMM1 rows)
#define ROWS2   3072            // B*LPOS*K        (GEMM2 rows)

// Output layout (float32, concatenated in reference return order)
#define OFF_H   0
#define OFF_S   1572864         // 3072*512
#define OFF_N   1575936
#define OFF_LK  1579008
#define OFF_RK  1582080

// Scratch (static device globals: allocation-free per harness rules)
__device__ float g_U[(size_t)ROWS1 * 512];   // ~100.7 MB
__device__ float g_H[(size_t)ROWS2 * 512];   // ~6.3 MB
__device__ int   g_li[NIDX];
__device__ int   g_ri[NIDX];
__device__ int4  g_sel[ROWS2];

// ---------------------------------------------------------------------------
// K0: index conversion. Detects int32 vs int64 storage of l_index/r_index.
// l_index[0]=0, l_index[1]=64 by construction, so:
//   int32: words = {0, 64, 127, ...}
//   int64: words = {0, 0, 64, 0, ...}
__global__ void conv_idx_kernel(const void* __restrict__ lraw,
                                const void* __restrict__ rraw) {
    const int* w = (const int*)lraw;
    bool is64 = (w[1] == 0 && w[2] == 64);
    int t = blockIdx.x * blockDim.x + threadIdx.x;
    if (t < NIDX) {
        if (is64) {
            g_li[t] = (int)((const long long*)lraw)[t];
            g_ri[t] = (int)((const long long*)rraw)[t];
        } else {
            g_li[t] = ((const int*)lraw)[t];
            g_ri[t] = ((const int*)rraw)[t];
        }
    }
}

// ---------------------------------------------------------------------------
// K1: U = gather(chart_h at left cells) @ mat
// Row r = ((b*48 + l)*16 + n)*2 + k   -> U[r][:] = chart_h[k,b,lcell] @ mat
// 128x128 tile, BK=8, 256 threads, 8x8 per thread.
__global__ __launch_bounds__(256) void gemm1_kernel(
    const float* __restrict__ chart_h, const float* __restrict__ mat) {
    __shared__ float As[8][128];
    __shared__ float Bs[8][128];
    __shared__ const float* Arow[128];

    int tid  = threadIdx.x;
    int row0 = blockIdx.y * 128;
    int col0 = blockIdx.x * 128;

    if (tid < 128) {
        int r = row0 + tid;
        int k = r & 1;
        int t = r >> 1;
        int n = t & 15;
        int bl = t >> 4;
        int l = bl % LPOS, b = bl / LPOS;
        int cell = g_li[(l << 4) + n];
        Arow[tid] = chart_h + (((size_t)(k * BATCH + b)) * NCELLS + cell) * SIZE;
    }
    __syncthreads();

    float acc[8][8];
#pragma unroll
    for (int i = 0; i < 8; i++)
#pragma unroll
        for (int j = 0; j < 8; j++) acc[i][j] = 0.f;

    int arow  = tid >> 1;
    int acol4 = (tid & 1) * 4;
    int brow  = tid >> 5;
    int bcol4 = (tid & 31) * 4;
    int ty = tid >> 4, tx = tid & 15;

    for (int kk = 0; kk < 512; kk += 8) {
        float4 av = *(const float4*)(Arow[arow] + kk + acol4);
        As[acol4 + 0][arow] = av.x;
        As[acol4 + 1][arow] = av.y;
        As[acol4 + 2][arow] = av.z;
        As[acol4 + 3][arow] = av.w;
        *(float4*)(&Bs[brow][bcol4]) =
            *(const float4*)(mat + (size_t)(kk + brow) * 512 + col0 + bcol4);
        __syncthreads();
#pragma unroll
        for (int kq = 0; kq < 8; kq++) {
            float a[8], bb[8];
#pragma unroll
            for (int i = 0; i < 8; i++) a[i] = As[kq][ty * 8 + i];
#pragma unroll
            for (int j = 0; j < 8; j++) bb[j] = Bs[kq][tx * 8 + j];
#pragma unroll
            for (int i = 0; i < 8; i++)
#pragma unroll
                for (int j = 0; j < 8; j++) acc[i][j] += a[i] * bb[j];
        }
        __syncthreads();
    }
#pragma unroll
    for (int i = 0; i < 8; i++) {
        int r = row0 + ty * 8 + i;
        float* crow = g_U + (size_t)r * 512 + col0 + tx * 8;
#pragma unroll
        for (int j = 0; j < 8; j += 4) {
            float4 v = make_float4(acc[i][j], acc[i][j+1], acc[i][j+2], acc[i][j+3]);
            *(float4*)(crow + j) = v;
        }
    }
}

// ---------------------------------------------------------------------------
// K2: per (b,l): 64 bilinear scores = U . rh + ls + rs, penalty, top-2,
// write topk_s / indices, record selection for the compose GEMM.
__global__ __launch_bounds__(256) void score_topk_kernel(
    const float* __restrict__ chart_h, const float* __restrict__ chart_s,
    float* __restrict__ out) {
    int bl = blockIdx.x;                 // 0..1535
    int b = bl / LPOS, l = bl % LPOS;
    int warp = threadIdx.x >> 5;
    int lane = threadIdx.x & 31;

    __shared__ float s[64];

    for (int n = warp; n < 16; n += 8) {
        int lcell = g_li[(l << 4) + n];
        int rcell = g_ri[(l << 4) + n];
        const float* u0 = g_U + ((((size_t)bl * 16) + n) * 2 + 0) * 512;
        const float* u1 = u0 + 512;
        const float* r0 = chart_h + (((size_t)(0 * BATCH + b)) * NCELLS + rcell) * SIZE;
        const float* r1 = chart_h + (((size_t)(1 * BATCH + b)) * NCELLS + rcell) * SIZE;
        float a00 = 0.f, a01 = 0.f, a10 = 0.f, a11 = 0.f;
        for (int i = lane; i < 512; i += 32) {
            float x0 = u0[i], x1 = u1[i], y0 = r0[i], y1 = r1[i];
            a00 += x0 * y0; a01 += x0 * y1;
            a10 += x1 * y0; a11 += x1 * y1;
        }
#pragma unroll
        for (int o = 16; o; o >>= 1) {
            a00 += __shfl_xor_sync(0xffffffffu, a00, o);
            a01 += __shfl_xor_sync(0xffffffffu, a01, o);
            a10 += __shfl_xor_sync(0xffffffffu, a10, o);
            a11 += __shfl_xor_sync(0xffffffffu, a11, o);
        }
        if (lane == 0) {
            float ls0 = chart_s[(size_t)(0 * BATCH + b) * NCELLS + lcell];
            float ls1 = chart_s[(size_t)(1 * BATCH + b) * NCELLS + lcell];
            float rs0 = chart_s[(size_t)(0 * BATCH + b) * NCELLS + rcell];
            float rs1 = chart_s[(size_t)(1 * BATCH + b) * NCELLS + rcell];
            float v00 = a00 + ls0 + rs0, v01 = a01 + ls0 + rs1;
            float v10 = a10 + ls1 + rs0, v11 = a11 + ls1 + rs1;
            if (n == 0) { v10 = NEG; v11 = NEG; }   // penalty: catalan(1)=1 < lk+1 for lk=1
            s[n * 4 + 0] = v00; s[n * 4 + 1] = v01;
            s[n * 4 + 2] = v10; s[n * 4 + 3] = v11;
        }
    }
    __syncthreads();

    if (threadIdx.x == 0) {
        float b1 = -INFINITY; int i1 = 0;
        for (int z = 0; z < 64; z++) { float v = s[z]; if (v > b1) { b1 = v; i1 = z; } }
        float b2 = -INFINITY; int i2 = 0;
        for (int z = 0; z < 64; z++) {
            if (z == i1) continue;
            float v = s[z]; if (v > b2) { b2 = v; i2 = z; }
        }
        int base = bl * 2;
        out[OFF_S  + base]     = b1;
        out[OFF_S  + base + 1] = b2;
        out[OFF_N  + base]     = (float)(i1 >> 2);
        out[OFF_N  + base + 1] = (float)(i2 >> 2);
        out[OFF_LK + base]     = (float)((i1 >> 1) & 1);
        out[OFF_LK + base + 1] = (float)((i2 >> 1) & 1);
        out[OFF_RK + base]     = (float)(i1 & 1);
        out[OFF_RK + base + 1] = (float)(i2 & 1);
        g_sel[base]     = make_int4(i1 >> 2, (i1 >> 1) & 1, i1 & 1, 0);
        g_sel[base + 1] = make_int4(i2 >> 2, (i2 >> 1) & 1, i2 & 1, 0);
    }
}

// ---------------------------------------------------------------------------
// K3: H = tanh([lh_sel ; rh_sel] @ Wc + bc) for the 3072 selected rows.
__global__ __launch_bounds__(256) void gemm2_kernel(
    const float* __restrict__ chart_h, const float* __restrict__ Wc,
    const float* __restrict__ bc) {
    __shared__ float As[8][128];
    __shared__ float Bs[8][128];
    __shared__ const float* ArowL[128];
    __shared__ const float* ArowR[128];

    int tid  = threadIdx.x;
    int row0 = blockIdx.y * 128;
    int col0 = blockIdx.x * 128;

    if (tid < 128) {
        int r = row0 + tid;
        int bl = r >> 1;
        int b = bl / LPOS, l = bl % LPOS;
        int4 sel = g_sel[r];
        int lcell = g_li[(l << 4) + sel.x];
        int rcell = g_ri[(l << 4) + sel.x];
        ArowL[tid] = chart_h + (((size_t)(sel.y * BATCH + b)) * NCELLS + lcell) * SIZE;
        ArowR[tid] = chart_h + (((size_t)(sel.z * BATCH + b)) * NCELLS + rcell) * SIZE;
    }
    __syncthreads();

    float acc[8][8];
#pragma unroll
    for (int i = 0; i < 8; i++)
#pragma unroll
        for (int j = 0; j < 8; j++) acc[i][j] = 0.f;

    int arow  = tid >> 1;
    int acol4 = (tid & 1) * 4;
    int brow  = tid >> 5;
    int bcol4 = (tid & 31) * 4;
    int ty = tid >> 4, tx = tid & 15;

    for (int kk = 0; kk < 1024; kk += 8) {
        const float* src = (kk < 512) ? (ArowL[arow] + kk) : (ArowR[arow] + (kk - 512));
        float4 av = *(const float4*)(src + acol4);
        As[acol4 + 0][arow] = av.x;
        As[acol4 + 1][arow] = av.y;
        As[acol4 + 2][arow] = av.z;
        As[acol4 + 3][arow] = av.w;
        *(float4*)(&Bs[brow][bcol4]) =
            *(const float4*)(Wc + (size_t)(kk + brow) * 512 + col0 + bcol4);
        __syncthreads();
#pragma unroll
        for (int kq = 0; kq < 8; kq++) {
            float a[8], bb[8];
#pragma unroll
            for (int i = 0; i < 8; i++) a[i] = As[kq][ty * 8 + i];
#pragma unroll
            for (int j = 0; j < 8; j++) bb[j] = Bs[kq][tx * 8 + j];
#pragma unroll
            for (int i = 0; i < 8; i++)
#pragma unroll
                for (int j = 0; j < 8; j++) acc[i][j] += a[i] * bb[j];
        }
        __syncthreads();
    }
#pragma unroll
    for (int i = 0; i < 8; i++) {
        int r = row0 + ty * 8 + i;
#pragma unroll
        for (int j = 0; j < 8; j++) {
            int col = col0 + tx * 8 + j;
            g_H[(size_t)r * 512 + col] = tanhf(acc[i][j] + bc[col]);
        }
    }
}

// ---------------------------------------------------------------------------
// K4: unit-normalize each selected row, write topk_h.
__global__ __launch_bounds__(256) void normalize_kernel(float* __restrict__ out) {
    int r = blockIdx.x;                   // 0..3071
    const float* h = g_H + (size_t)r * 512;
    int t = threadIdx.x;
    float v0 = h[t], v1 = h[t + 256];
    float ss = v0 * v0 + v1 * v1;
#pragma unroll
    for (int o = 16; o; o >>= 1) ss += __shfl_xor_sync(0xffffffffu, ss, o);
    __shared__ float red[8];
    __shared__ float s_inv;
    if ((t & 31) == 0) red[t >> 5] = ss;
    __syncthreads();
    if (t == 0) {
        float x = 0.f;
#pragma unroll
        for (int i = 0; i < 8; i++) x += red[i];
        s_inv = 1.0f / sqrtf(x);
    }
    __syncthreads();
    float inv = s_inv;
    out[OFF_H + (size_t)r * 512 + t]       = v0 * inv;
    out[OFF_H + (size_t)r * 512 + t + 256] = v1 * inv;
}

// ---------------------------------------------------------------------------
extern "C" void kernel_launch(void* const* d_in, const int* in_sizes, int n_in,
                              void* d_out, int out_size) {
    const float* chart_h = (const float*)d_in[0];
    const float* chart_s = (const float*)d_in[1];
    const void*  l_index = d_in[2];
    const void*  r_index = d_in[3];
    const float* mat     = (const float*)d_in[4];
    const float* Wc      = (const float*)d_in[5];
    const float* bc      = (const float*)d_in[6];
    float* out = (float*)d_out;

    conv_idx_kernel<<<1, NIDX>>>(l_index, r_index);
    gemm1_kernel<<<dim3(4, ROWS1 / 128), 256>>>(chart_h, mat);
    score_topk_kernel<<<BATCH * LPOS, 256>>>(chart_h, chart_s, out);
    gemm2_kernel<<<dim3(4, ROWS2 / 128), 256>>>(chart_h, Wc, bc);
    normalize_kernel<<<ROWS2, 256>>>(out);
}

// round 2
// speedup vs baseline: 1.0074x; 1.0074x over previous
#include <cuda_runtime.h>
#include <math.h>

// Problem constants
#define LEVEL   16
#define LENGTH  64
#define TOPK    2
#define SIZE    512
#define BATCH   32
#define NEG     (-1e8f)

#define LPOS    48              // LENGTH - LEVEL
#define NCELLS  904
#define NIDX    768             // LPOS * LEVEL
#define ROWS1   49152           // K*B*LPOS*LEVEL  (GEMM1 rows)
#define ROWS2   3072            // B*LPOS*K        (GEMM2 rows)
#define KSPLIT  4

// Output layout (float32, concatenated in reference return order)
#define OFF_H   0
#define OFF_S   1572864         // 3072*512
#define OFF_N   1575936
#define OFF_LK  1579008
#define OFF_RK  1582080

// Scratch (static device globals: allocation-free per harness rules)
__device__ float g_U[(size_t)ROWS1 * 512];              // ~100.7 MB
__device__ float g_P[(size_t)KSPLIT * ROWS2 * 512];     // ~25 MB split-K partials
__device__ int   g_li[NIDX];
__device__ int   g_ri[NIDX];
__device__ int4  g_sel[ROWS2];

typedef unsigned long long u64t;

// packed f32x2 FMA: acc = a*b + acc (2 lanes per instruction)
#define FFMA2(acc, a, b) \
    asm("fma.rn.f32x2 %0, %1, %2, %0;" : "+l"(acc) : "l"(a), "l"(b))

// ---------------------------------------------------------------------------
// K0: index conversion. Detects int32 vs int64 storage of l_index/r_index.
__global__ void conv_idx_kernel(const void* __restrict__ lraw,
                                const void* __restrict__ rraw) {
    const int* w = (const int*)lraw;
    bool is64 = (w[1] == 0 && w[2] == 64);
    int t = blockIdx.x * blockDim.x + threadIdx.x;
    if (t < NIDX) {
        if (is64) {
            g_li[t] = (int)((const long long*)lraw)[t];
            g_ri[t] = (int)((const long long*)rraw)[t];
        } else {
            g_li[t] = ((const int*)lraw)[t];
            g_ri[t] = ((const int*)rraw)[t];
        }
    }
}

// ---------------------------------------------------------------------------
// K1: U = gather(chart_h at left cells) @ mat
// 128x128 tile, BK=16, 256 threads, 8x8 per thread via packed f32x2 FMAs.
// As2 stores each A value DUPLICATED ({v,v}) so the inner loop gets the
// broadcast pair with a single LDS.64.
__global__ __launch_bounds__(256, 2) void gemm1_kernel(
    const float* __restrict__ chart_h, const float* __restrict__ mat) {
    __shared__ float As2[16][256];     // duplicated pairs
    __shared__ float Bs[16][128];
    __shared__ const float* Arow[128];

    int tid  = threadIdx.x;
    int row0 = blockIdx.y * 128;
    int col0 = blockIdx.x * 128;

    if (tid < 128) {
        int r = row0 + tid;
        int k = r & 1;
        int t = r >> 1;
        int n = t & 15;
        int bl = t >> 4;
        int l = bl % LPOS, b = bl / LPOS;
        int cell = g_li[(l << 4) + n];
        Arow[tid] = chart_h + (((size_t)(k * BATCH + b)) * NCELLS + cell) * SIZE;
    }
    __syncthreads();

    u64t acc[8][4];
#pragma unroll
    for (int i = 0; i < 8; i++)
#pragma unroll
        for (int j = 0; j < 4; j++) acc[i][j] = 0ull;

    int arow  = tid >> 1;
    int ahalf = (tid & 1) * 8;
    int brow  = tid >> 5;          // 0..7
    int bcol4 = (tid & 31) * 4;
    int ty = tid >> 4, tx = tid & 15;

    for (int kk = 0; kk < 512; kk += 16) {
        // fill A (dup pairs)
        float4 av0 = *(const float4*)(Arow[arow] + kk + ahalf);
        float4 av1 = *(const float4*)(Arow[arow] + kk + ahalf + 4);
        *(float2*)&As2[ahalf + 0][2 * arow] = make_float2(av0.x, av0.x);
        *(float2*)&As2[ahalf + 1][2 * arow] = make_float2(av0.y, av0.y);
        *(float2*)&As2[ahalf + 2][2 * arow] = make_float2(av0.z, av0.z);
        *(float2*)&As2[ahalf + 3][2 * arow] = make_float2(av0.w, av0.w);
        *(float2*)&As2[ahalf + 4][2 * arow] = make_float2(av1.x, av1.x);
        *(float2*)&As2[ahalf + 5][2 * arow] = make_float2(av1.y, av1.y);
        *(float2*)&As2[ahalf + 6][2 * arow] = make_float2(av1.z, av1.z);
        *(float2*)&As2[ahalf + 7][2 * arow] = make_float2(av1.w, av1.w);
        // fill B
        *(float4*)(&Bs[brow][bcol4]) =
            *(const float4*)(mat + (size_t)(kk + brow) * 512 + col0 + bcol4);
        *(float4*)(&Bs[brow + 8][bcol4]) =
            *(const float4*)(mat + (size_t)(kk + brow + 8) * 512 + col0 + bcol4);
        __syncthreads();
#pragma unroll
        for (int kq = 0; kq < 16; kq++) {
            u64t a2[8], b2[4];
#pragma unroll
            for (int i = 0; i < 8; i++)
                a2[i] = *(const u64t*)&As2[kq][2 * (ty * 8 + i)];
#pragma unroll
            for (int j = 0; j < 4; j++)
                b2[j] = ((const u64t*)&Bs[kq][tx * 8])[j];
#pragma unroll
            for (int i = 0; i < 8; i++)
#pragma unroll
                for (int j = 0; j < 4; j++) FFMA2(acc[i][j], a2[i], b2[j]);
        }
        __syncthreads();
    }
#pragma unroll
    for (int i = 0; i < 8; i++) {
        int r = row0 + ty * 8 + i;
        u64t* crow = (u64t*)(g_U + (size_t)r * 512 + col0 + tx * 8);
#pragma unroll
        for (int j = 0; j < 4; j++) crow[j] = acc[i][j];
    }
}

// ---------------------------------------------------------------------------
// K2: per (b,l): 64 bilinear scores = U . rh + ls + rs, penalty, top-2.
__global__ __launch_bounds__(256) void score_topk_kernel(
    const float* __restrict__ chart_h, const float* __restrict__ chart_s,
    float* __restrict__ out) {
    int bl = blockIdx.x;                 // 0..1535
    int b = bl / LPOS, l = bl % LPOS;
    int warp = threadIdx.x >> 5;
    int lane = threadIdx.x & 31;

    __shared__ float s[64];

    for (int n = warp; n < 16; n += 8) {
        int lcell = g_li[(l << 4) + n];
        int rcell = g_ri[(l << 4) + n];
        const float4* u0 = (const float4*)(g_U + ((((size_t)bl * 16) + n) * 2 + 0) * 512);
        const float4* u1 = u0 + 128;
        const float4* r0 = (const float4*)(chart_h + (((size_t)b) * NCELLS + rcell) * SIZE);
        const float4* r1 = (const float4*)(chart_h + (((size_t)(BATCH + b)) * NCELLS + rcell) * SIZE);
        float a00 = 0.f, a01 = 0.f, a10 = 0.f, a11 = 0.f;
#pragma unroll
        for (int it = 0; it < 4; it++) {
            int i = lane + it * 32;
            float4 x0 = u0[i], x1 = u1[i], y0 = r0[i], y1 = r1[i];
            a00 += x0.x*y0.x + x0.y*y0.y + x0.z*y0.z + x0.w*y0.w;
            a01 += x0.x*y1.x + x0.y*y1.y + x0.z*y1.z + x0.w*y1.w;
            a10 += x1.x*y0.x + x1.y*y0.y + x1.z*y0.z + x1.w*y0.w;
            a11 += x1.x*y1.x + x1.y*y1.y + x1.z*y1.z + x1.w*y1.w;
        }
#pragma unroll
        for (int o = 16; o; o >>= 1) {
            a00 += __shfl_xor_sync(0xffffffffu, a00, o);
            a01 += __shfl_xor_sync(0xffffffffu, a01, o);
            a10 += __shfl_xor_sync(0xffffffffu, a10, o);
            a11 += __shfl_xor_sync(0xffffffffu, a11, o);
        }
        if (lane == 0) {
            float ls0 = chart_s[(size_t)b * NCELLS + lcell];
            float ls1 = chart_s[(size_t)(BATCH + b) * NCELLS + lcell];
            float rs0 = chart_s[(size_t)b * NCELLS + rcell];
            float rs1 = chart_s[(size_t)(BATCH + b) * NCELLS + rcell];
            float v00 = a00 + ls0 + rs0, v01 = a01 + ls0 + rs1;
            float v10 = a10 + ls1 + rs0, v11 = a11 + ls1 + rs1;
            if (n == 0) { v10 = NEG; v11 = NEG; }   // penalty: catalan(1)=1 < lk+1 for lk=1
            s[n * 4 + 0] = v00; s[n * 4 + 1] = v01;
            s[n * 4 + 2] = v10; s[n * 4 + 3] = v11;
        }
    }
    __syncthreads();

    if (threadIdx.x == 0) {
        float b1 = -INFINITY; int i1 = 0;
        for (int z = 0; z < 64; z++) { float v = s[z]; if (v > b1) { b1 = v; i1 = z; } }
        float b2 = -INFINITY; int i2 = 0;
        for (int z = 0; z < 64; z++) {
            if (z == i1) continue;
            float v = s[z]; if (v > b2) { b2 = v; i2 = z; }
        }
        int base = bl * 2;
        out[OFF_S  + base]     = b1;
        out[OFF_S  + base + 1] = b2;
        out[OFF_N  + base]     = (float)(i1 >> 2);
        out[OFF_N  + base + 1] = (float)(i2 >> 2);
        out[OFF_LK + base]     = (float)((i1 >> 1) & 1);
        out[OFF_LK + base + 1] = (float)((i2 >> 1) & 1);
        out[OFF_RK + base]     = (float)(i1 & 1);
        out[OFF_RK + base + 1] = (float)(i2 & 1);
        g_sel[base]     = make_int4(i1 >> 2, (i1 >> 1) & 1, i1 & 1, 0);
        g_sel[base + 1] = make_int4(i2 >> 2, (i2 >> 1) & 1, i2 & 1, 0);
    }
}

// ---------------------------------------------------------------------------
// K3: split-K compose GEMM. Each block: 128 rows x 128 cols x 256 K-slice.
// ks<2 reads left-child halves, ks>=2 right-child halves. Partials -> g_P.
__global__ __launch_bounds__(256, 2) void gemm2_kernel(
    const float* __restrict__ chart_h, const float* __restrict__ Wc) {
    __shared__ float As2[16][256];
    __shared__ float Bs[16][128];
    __shared__ const float* Arow[128];

    int tid  = threadIdx.x;
    int row0 = blockIdx.y * 128;
    int col0 = blockIdx.x * 128;
    int ks   = blockIdx.z;
    int kbase = ks * 256;                 // global K offset in [0,1024)

    if (tid < 128) {
        int r = row0 + tid;
        int bl = r >> 1;
        int b = bl / LPOS, l = bl % LPOS;
        int4 sel = g_sel[r];
        const float* base;
        if (kbase < 512) {
            int lcell = g_li[(l << 4) + sel.x];
            base = chart_h + (((size_t)(sel.y * BATCH + b)) * NCELLS + lcell) * SIZE + kbase;
        } else {
            int rcell = g_ri[(l << 4) + sel.x];
            base = chart_h + (((size_t)(sel.z * BATCH + b)) * NCELLS + rcell) * SIZE + (kbase - 512);
        }
        Arow[tid] = base;
    }
    __syncthreads();

    u64t acc[8][4];
#pragma unroll
    for (int i = 0; i < 8; i++)
#pragma unroll
        for (int j = 0; j < 4; j++) acc[i][j] = 0ull;

    int arow  = tid >> 1;
    int ahalf = (tid & 1) * 8;
    int brow  = tid >> 5;
    int bcol4 = (tid & 31) * 4;
    int ty = tid >> 4, tx = tid & 15;

    for (int kk = 0; kk < 256; kk += 16) {
        float4 av0 = *(const float4*)(Arow[arow] + kk + ahalf);
        float4 av1 = *(const float4*)(Arow[arow] + kk + ahalf + 4);
        *(float2*)&As2[ahalf + 0][2 * arow] = make_float2(av0.x, av0.x);
        *(float2*)&As2[ahalf + 1][2 * arow] = make_float2(av0.y, av0.y);
        *(float2*)&As2[ahalf + 2][2 * arow] = make_float2(av0.z, av0.z);
        *(float2*)&As2[ahalf + 3][2 * arow] = make_float2(av0.w, av0.w);
        *(float2*)&As2[ahalf + 4][2 * arow] = make_float2(av1.x, av1.x);
        *(float2*)&As2[ahalf + 5][2 * arow] = make_float2(av1.y, av1.y);
        *(float2*)&As2[ahalf + 6][2 * arow] = make_float2(av1.z, av1.z);
        *(float2*)&As2[ahalf + 7][2 * arow] = make_float2(av1.w, av1.w);
        int kg = kbase + kk;
        *(float4*)(&Bs[brow][bcol4]) =
            *(const float4*)(Wc + (size_t)(kg + brow) * 512 + col0 + bcol4);
        *(float4*)(&Bs[brow + 8][bcol4]) =
            *(const float4*)(Wc + (size_t)(kg + brow + 8) * 512 + col0 + bcol4);
        __syncthreads();
#pragma unroll
        for (int kq = 0; kq < 16; kq++) {
            u64t a2[8], b2[4];
#pragma unroll
            for (int i = 0; i < 8; i++)
                a2[i] = *(const u64t*)&As2[kq][2 * (ty * 8 + i)];
#pragma unroll
            for (int j = 0; j < 4; j++)
                b2[j] = ((const u64t*)&Bs[kq][tx * 8])[j];
#pragma unroll
            for (int i = 0; i < 8; i++)
#pragma unroll
                for (int j = 0; j < 4; j++) FFMA2(acc[i][j], a2[i], b2[j]);
        }
        __syncthreads();
    }
#pragma unroll
    for (int i = 0; i < 8; i++) {
        int r = row0 + ty * 8 + i;
        u64t* crow = (u64t*)(g_P + ((size_t)ks * ROWS2 + r) * 512 + col0 + tx * 8);
#pragma unroll
        for (int j = 0; j < 4; j++) crow[j] = acc[i][j];
    }
}

// ---------------------------------------------------------------------------
// K4: combine split-K partials + bias + tanh + unit-norm, write topk_h.
__global__ __launch_bounds__(256) void combine_normalize_kernel(
    const float* __restrict__ bc, float* __restrict__ out) {
    int r = blockIdx.x;                   // 0..3071
    int t = threadIdx.x;
    const float* p = g_P + (size_t)r * 512;
    const size_t stride = (size_t)ROWS2 * 512;

    float v0 = bc[t]       + p[t]       + p[t + stride]       + p[t + 2*stride]       + p[t + 3*stride];
    float v1 = bc[t + 256] + p[t + 256] + p[t + 256 + stride] + p[t + 256 + 2*stride] + p[t + 256 + 3*stride];
    v0 = tanhf(v0);
    v1 = tanhf(v1);

    float ss = v0 * v0 + v1 * v1;
#pragma unroll
    for (int o = 16; o; o >>= 1) ss += __shfl_xor_sync(0xffffffffu, ss, o);
    __shared__ float red[8];
    __shared__ float s_inv;
    if ((t & 31) == 0) red[t >> 5] = ss;
    __syncthreads();
    if (t == 0) {
        float x = 0.f;
#pragma unroll
        for (int i = 0; i < 8; i++) x += red[i];
        s_inv = 1.0f / sqrtf(x);
    }
    __syncthreads();
    float inv = s_inv;
    out[OFF_H + (size_t)r * 512 + t]       = v0 * inv;
    out[OFF_H + (size_t)r * 512 + t + 256] = v1 * inv;
}

// ---------------------------------------------------------------------------
extern "C" void kernel_launch(void* const* d_in, const int* in_sizes, int n_in,
                              void* d_out, int out_size) {
    const float* chart_h = (const float*)d_in[0];
    const float* chart_s = (const float*)d_in[1];
    const void*  l_index = d_in[2];
    const void*  r_index = d_in[3];
    const float* mat     = (const float*)d_in[4];
    const float* Wc      = (const float*)d_in[5];
    const float* bc      = (const float*)d_in[6];
    float* out = (float*)d_out;

    conv_idx_kernel<<<3, 256>>>(l_index, r_index);
    gemm1_kernel<<<dim3(4, ROWS1 / 128), 256>>>(chart_h, mat);
    score_topk_kernel<<<BATCH * LPOS, 256>>>(chart_h, chart_s, out);
    gemm2_kernel<<<dim3(4, ROWS2 / 128, KSPLIT), 256>>>(chart_h, Wc);
    combine_normalize_kernel<<<ROWS2, 256>>>(bc, out);
}

// round 3
// speedup vs baseline: 1.0871x; 1.0792x over previous
#include <cuda_runtime.h>
#include <math.h>
#include <stdint.h>

// Problem constants
#define LEVEL   16
#define LENGTH  64
#define TOPK    2
#define SIZE    512
#define BATCH   32
#define NEG     (-1e8f)

#define LPOS    48              // LENGTH - LEVEL
#define NCELLS  904
#define NIDX    768             // LPOS * LEVEL
#define ROWS1   49152           // K*B*LPOS*LEVEL  (GEMM1 rows)
#define ROWS2   3072            // B*LPOS*K        (GEMM2 rows)
#define KSPLIT  4
#define NCELLS_BL 1536          // BATCH*LPOS
#define MAXCAND 8
#define MAXROWS (NCELLS_BL * MAXCAND)   // 12288
#define DELTA   0.5f

// Output layout (float32, concatenated in reference return order)
#define OFF_H   0
#define OFF_S   1572864         // 3072*512
#define OFF_N   1575936
#define OFF_LK  1579008
#define OFF_RK  1582080

// Scratch (static device globals: allocation-free per harness rules)
__device__ float g_U[(size_t)ROWS1 * 512];              // ~100.7 MB (tf32-approx)
__device__ float g_P[(size_t)KSPLIT * ROWS2 * 512];     // ~25 MB split-K partials
__device__ float g_Z[(size_t)MAXROWS * 512];            // ~25 MB exact rescore
__device__ int   g_li[NIDX];
__device__ int   g_ri[NIDX];
__device__ int4  g_sel[ROWS2];
__device__ int   g_nrows;
__device__ int   g_rows[MAXROWS];      // (bl<<6)|z
__device__ float g_sexact[MAXROWS];
__device__ int   g_cellbase[NCELLS_BL];
__device__ int   g_cellcnt[NCELLS_BL];

typedef unsigned long long u64t;

// packed f32x2 FMA: acc = a*b + acc (2 lanes per instruction)
#define FFMA2(acc, a, b) \
    asm("fma.rn.f32x2 %0, %1, %2, %0;" : "+l"(acc) : "l"(a), "l"(b))

__device__ __forceinline__ void mma_tf32(float d[4],
        uint32_t a0, uint32_t a1, uint32_t a2, uint32_t a3,
        uint32_t b0, uint32_t b1) {
    asm volatile(
        "mma.sync.aligned.m16n8k8.row.col.f32.tf32.tf32.f32 "
        "{%0,%1,%2,%3}, {%4,%5,%6,%7}, {%8,%9}, {%0,%1,%2,%3};"
        : "+f"(d[0]), "+f"(d[1]), "+f"(d[2]), "+f"(d[3])
        : "r"(a0), "r"(a1), "r"(a2), "r"(a3), "r"(b0), "r"(b1));
}

// ---------------------------------------------------------------------------
// K0: index conversion + counter reset.
__global__ void conv_idx_kernel(const void* __restrict__ lraw,
                                const void* __restrict__ rraw) {
    if (blockIdx.x == 0 && threadIdx.x == 0) g_nrows = 0;
    const int* w = (const int*)lraw;
    bool is64 = (w[1] == 0 && w[2] == 64);
    int t = blockIdx.x * blockDim.x + threadIdx.x;
    if (t < NIDX) {
        if (is64) {
            g_li[t] = (int)((const long long*)lraw)[t];
            g_ri[t] = (int)((const long long*)rraw)[t];
        } else {
            g_li[t] = ((const int*)lraw)[t];
            g_ri[t] = ((const int*)rraw)[t];
        }
    }
}

// ---------------------------------------------------------------------------
// K1: U_approx = gather(chart_h left cells) @ mat via mma.sync tf32.
// Block: 128x128 tile, BK=32, 256 thr = 8 warps (2x4), warp tile 64x32.
__global__ __launch_bounds__(256, 2) void gemm1_tf32_kernel(
    const float* __restrict__ chart_h, const float* __restrict__ mat) {
    __shared__ float As[128][36];      // +4 pad: conflict-free frag loads
    __shared__ float Bs[32][132];      // +4 pad
    __shared__ const float* Arow[128];

    int tid  = threadIdx.x;
    int row0 = blockIdx.y * 128;
    int col0 = blockIdx.x * 128;

    if (tid < 128) {
        int r = row0 + tid;
        int k = r & 1;
        int t = r >> 1;
        int n = t & 15;
        int bl = t >> 4;
        int l = bl % LPOS, b = bl / LPOS;
        int cell = g_li[(l << 4) + n];
        Arow[tid] = chart_h + (((size_t)(k * BATCH + b)) * NCELLS + cell) * SIZE;
    }
    __syncthreads();

    int wid = tid >> 5, lane = tid & 31;
    int wm = wid >> 2, wn = wid & 3;          // warp grid 2(M) x 4(N)
    int gid = lane >> 2, tig = lane & 3;

    float d[4][4][4];
#pragma unroll
    for (int mf = 0; mf < 4; mf++)
#pragma unroll
        for (int nf = 0; nf < 4; nf++)
#pragma unroll
            for (int c = 0; c < 4; c++) d[mf][nf][c] = 0.f;

    int ar = tid >> 1, ac = (tid & 1) * 16;   // A: 2 thr/row, 16 floats each
    int br = tid >> 3, bc = (tid & 7) * 16;   // B: 8 thr/row, 16 floats each

    for (int kt = 0; kt < 16; kt++) {
        int kb = kt * 32;
        float4 av[4], bv[4];
#pragma unroll
        for (int j = 0; j < 4; j++) {
            av[j] = *(const float4*)(Arow[ar] + kb + ac + 4 * j);
            bv[j] = *(const float4*)(mat + (size_t)(kb + br) * 512 + col0 + bc + 4 * j);
        }
        __syncthreads();
#pragma unroll
        for (int j = 0; j < 4; j++) {
            *(float4*)&As[ar][ac + 4 * j] = av[j];
            *(float4*)&Bs[br][bc + 4 * j] = bv[j];
        }
        __syncthreads();
#pragma unroll
        for (int kf = 0; kf < 4; kf++) {
            int k0 = kf * 8;
            uint32_t a[4][4], b[4][2];
#pragma unroll
            for (int mf = 0; mf < 4; mf++) {
                int m = wm * 64 + mf * 16 + gid;
                a[mf][0] = __float_as_uint(As[m][k0 + tig]);
                a[mf][1] = __float_as_uint(As[m + 8][k0 + tig]);
                a[mf][2] = __float_as_uint(As[m][k0 + tig + 4]);
                a[mf][3] = __float_as_uint(As[m + 8][k0 + tig + 4]);
            }
#pragma unroll
            for (int nf = 0; nf < 4; nf++) {
                int nn = wn * 32 + nf * 8 + gid;
                b[nf][0] = __float_as_uint(Bs[k0 + tig][nn]);
                b[nf][1] = __float_as_uint(Bs[k0 + tig + 4][nn]);
            }
#pragma unroll
            for (int mf = 0; mf < 4; mf++)
#pragma unroll
                for (int nf = 0; nf < 4; nf++)
                    mma_tf32(d[mf][nf], a[mf][0], a[mf][1], a[mf][2], a[mf][3],
                             b[nf][0], b[nf][1]);
        }
    }
#pragma unroll
    for (int mf = 0; mf < 4; mf++) {
        int rA = row0 + wm * 64 + mf * 16 + gid;
#pragma unroll
        for (int nf = 0; nf < 4; nf++) {
            int cA = col0 + wn * 32 + nf * 8 + tig * 2;
            *(float2*)(g_U + (size_t)rA * 512 + cA)       = make_float2(d[mf][nf][0], d[mf][nf][1]);
            *(float2*)(g_U + (size_t)(rA + 8) * 512 + cA) = make_float2(d[mf][nf][2], d[mf][nf][3]);
        }
    }
}

// ---------------------------------------------------------------------------
// K2: approximate scores + candidate nomination (within DELTA of approx 2nd).
__global__ __launch_bounds__(256) void score_approx_kernel(
    const float* __restrict__ chart_h, const float* __restrict__ chart_s) {
    int bl = blockIdx.x;                 // 0..1535
    int b = bl / LPOS, l = bl % LPOS;
    int warp = threadIdx.x >> 5;
    int lane = threadIdx.x & 31;

    __shared__ float s[64];

    for (int n = warp; n < 16; n += 8) {
        int lcell = g_li[(l << 4) + n];
        int rcell = g_ri[(l << 4) + n];
        const float4* u0 = (const float4*)(g_U + ((((size_t)bl * 16) + n) * 2 + 0) * 512);
        const float4* u1 = u0 + 128;
        const float4* r0 = (const float4*)(chart_h + (((size_t)b) * NCELLS + rcell) * SIZE);
        const float4* r1 = (const float4*)(chart_h + (((size_t)(BATCH + b)) * NCELLS + rcell) * SIZE);
        float a00 = 0.f, a01 = 0.f, a10 = 0.f, a11 = 0.f;
#pragma unroll
        for (int it = 0; it < 4; it++) {
            int i = lane + it * 32;
            float4 x0 = u0[i], x1 = u1[i], y0 = r0[i], y1 = r1[i];
            a00 += x0.x*y0.x + x0.y*y0.y + x0.z*y0.z + x0.w*y0.w;
            a01 += x0.x*y1.x + x0.y*y1.y + x0.z*y1.z + x0.w*y1.w;
            a10 += x1.x*y0.x + x1.y*y0.y + x1.z*y0.z + x1.w*y0.w;
            a11 += x1.x*y1.x + x1.y*y1.y + x1.z*y1.z + x1.w*y1.w;
        }
#pragma unroll
        for (int o = 16; o; o >>= 1) {
            a00 += __shfl_xor_sync(0xffffffffu, a00, o);
            a01 += __shfl_xor_sync(0xffffffffu, a01, o);
            a10 += __shfl_xor_sync(0xffffffffu, a10, o);
            a11 += __shfl_xor_sync(0xffffffffu, a11, o);
        }
        if (lane == 0) {
            float ls0 = chart_s[(size_t)b * NCELLS + lcell];
            float ls1 = chart_s[(size_t)(BATCH + b) * NCELLS + lcell];
            float rs0 = chart_s[(size_t)b * NCELLS + rcell];
            float rs1 = chart_s[(size_t)(BATCH + b) * NCELLS + rcell];
            float v00 = a00 + ls0 + rs0, v01 = a01 + ls0 + rs1;
            float v10 = a10 + ls1 + rs0, v11 = a11 + ls1 + rs1;
            if (n == 0) { v10 = NEG; v11 = NEG; }   // penalty combos can never win
            s[n * 4 + 0] = v00; s[n * 4 + 1] = v01;
            s[n * 4 + 2] = v10; s[n * 4 + 3] = v11;
        }
    }
    __syncthreads();

    if (threadIdx.x == 0) {
        float b1 = -INFINITY; int i1 = 0;
        for (int z = 0; z < 64; z++) { float v = s[z]; if (v > b1) { b1 = v; i1 = z; } }
        float b2 = -INFINITY; int i2 = 0;
        for (int z = 0; z < 64; z++) {
            if (z == i1) continue;
            float v = s[z]; if (v > b2) { b2 = v; i2 = z; }
        }
        float thr = b2 - DELTA;
        int cand[MAXCAND];
        int cnt = 0;
        cand[cnt++] = i1;
        cand[cnt++] = i2;
        for (int z = 0; z < 64 && cnt < MAXCAND; z++) {
            if (z == i1 || z == i2) continue;
            if (s[z] >= thr) cand[cnt++] = z;
        }
        int base = atomicAdd(&g_nrows, cnt);
        g_cellbase[bl] = base;
        g_cellcnt[bl]  = cnt;
        for (int c = 0; c < cnt; c++) g_rows[base + c] = (bl << 6) | cand[c];
    }
}

// ---------------------------------------------------------------------------
// K3: exact rescore GEMM: Z = LhCand @ mat  (fp32, FFMA2 tiles, ~1 G-FMA).
__global__ __launch_bounds__(256, 2) void rescore_gemm_kernel(
    const float* __restrict__ chart_h, const float* __restrict__ mat) {
    int nrows = g_nrows;
    if ((int)(blockIdx.y * 128) >= nrows) return;

    __shared__ float As2[16][256];
    __shared__ float Bs[16][128];
    __shared__ const float* Arow[128];

    int tid  = threadIdx.x;
    int row0 = blockIdx.y * 128;
    int col0 = blockIdx.x * 128;

    if (tid < 128) {
        int r = row0 + tid;
        const float* p = chart_h;       // dummy for padded rows
        if (r < nrows) {
            int code = g_rows[r];
            int bl = code >> 6, z = code & 63;
            int n = z >> 2, kl = (z >> 1) & 1;
            int b = bl / LPOS, l = bl % LPOS;
            int lcell = g_li[(l << 4) + n];
            p = chart_h + (((size_t)(kl * BATCH + b)) * NCELLS + lcell) * SIZE;
        }
        Arow[tid] = p;
    }
    __syncthreads();

    u64t acc[8][4];
#pragma unroll
    for (int i = 0; i < 8; i++)
#pragma unroll
        for (int j = 0; j < 4; j++) acc[i][j] = 0ull;

    int arow  = tid >> 1;
    int ahalf = (tid & 1) * 8;
    int brow  = tid >> 5;
    int bcol4 = (tid & 31) * 4;
    int ty = tid >> 4, tx = tid & 15;

    for (int kk = 0; kk < 512; kk += 16) {
        float4 av0 = *(const float4*)(Arow[arow] + kk + ahalf);
        float4 av1 = *(const float4*)(Arow[arow] + kk + ahalf + 4);
        *(float2*)&As2[ahalf + 0][2 * arow] = make_float2(av0.x, av0.x);
        *(float2*)&As2[ahalf + 1][2 * arow] = make_float2(av0.y, av0.y);
        *(float2*)&As2[ahalf + 2][2 * arow] = make_float2(av0.z, av0.z);
        *(float2*)&As2[ahalf + 3][2 * arow] = make_float2(av0.w, av0.w);
        *(float2*)&As2[ahalf + 4][2 * arow] = make_float2(av1.x, av1.x);
        *(float2*)&As2[ahalf + 5][2 * arow] = make_float2(av1.y, av1.y);
        *(float2*)&As2[ahalf + 6][2 * arow] = make_float2(av1.z, av1.z);
        *(float2*)&As2[ahalf + 7][2 * arow] = make_float2(av1.w, av1.w);
        *(float4*)(&Bs[brow][bcol4]) =
            *(const float4*)(mat + (size_t)(kk + brow) * 512 + col0 + bcol4);
        *(float4*)(&Bs[brow + 8][bcol4]) =
            *(const float4*)(mat + (size_t)(kk + brow + 8) * 512 + col0 + bcol4);
        __syncthreads();
#pragma unroll
        for (int kq = 0; kq < 16; kq++) {
            u64t a2[8], b2[4];
#pragma unroll
            for (int i = 0; i < 8; i++)
                a2[i] = *(const u64t*)&As2[kq][2 * (ty * 8 + i)];
#pragma unroll
            for (int j = 0; j < 4; j++)
                b2[j] = ((const u64t*)&Bs[kq][tx * 8])[j];
#pragma unroll
            for (int i = 0; i < 8; i++)
#pragma unroll
                for (int j = 0; j < 4; j++) FFMA2(acc[i][j], a2[i], b2[j]);
        }
        __syncthreads();
    }
#pragma unroll
    for (int i = 0; i < 8; i++) {
        int r = row0 + ty * 8 + i;
        u64t* crow = (u64t*)(g_Z + (size_t)r * 512 + col0 + tx * 8);
#pragma unroll
        for (int j = 0; j < 4; j++) crow[j] = acc[i][j];
    }
}

// ---------------------------------------------------------------------------
// K4: exact score = Z[row] . rh + ls + rs. One warp per candidate row.
__global__ __launch_bounds__(256) void rescore_dot_kernel(
    const float* __restrict__ chart_h, const float* __restrict__ chart_s) {
    int nrows = g_nrows;
    int row = blockIdx.x * 8 + (threadIdx.x >> 5);
    if (row >= nrows) return;
    int lane = threadIdx.x & 31;

    int code = g_rows[row];
    int bl = code >> 6, z = code & 63;
    int n = z >> 2, kl = (z >> 1) & 1, kr = z & 1;
    int b = bl / LPOS, l = bl % LPOS;
    int lcell = g_li[(l << 4) + n];
    int rcell = g_ri[(l << 4) + n];

    const float4* zp = (const float4*)(g_Z + (size_t)row * 512);
    const float4* rh = (const float4*)(chart_h + (((size_t)(kr * BATCH + b)) * NCELLS + rcell) * SIZE);
    float a = 0.f;
#pragma unroll
    for (int it = 0; it < 4; it++) {
        int i = lane + it * 32;
        float4 x = zp[i], y = rh[i];
        a += x.x*y.x + x.y*y.y + x.z*y.z + x.w*y.w;
    }
#pragma unroll
    for (int o = 16; o; o >>= 1) a += __shfl_xor_sync(0xffffffffu, a, o);
    if (lane == 0) {
        float ls = chart_s[(size_t)(kl * BATCH + b) * NCELLS + lcell];
        float rs = chart_s[(size_t)(kr * BATCH + b) * NCELLS + rcell];
        g_sexact[row] = a + ls + rs;
    }
}

// ---------------------------------------------------------------------------
// K5: exact top-2 per cell from rescored candidates; write outputs + g_sel.
__global__ __launch_bounds__(256) void final_select_kernel(float* __restrict__ out) {
    int bl = blockIdx.x * 256 + threadIdx.x;
    if (bl >= NCELLS_BL) return;
    int base = g_cellbase[bl];
    int cnt  = g_cellcnt[bl];

    float s1 = -INFINITY, s2 = -INFINITY;
    int z1 = 64, z2 = 64;
    for (int c = 0; c < cnt; c++) {
        float v = g_sexact[base + c];
        int z = g_rows[base + c] & 63;
        if (v > s1 || (v == s1 && z < z1)) {
            s2 = s1; z2 = z1; s1 = v; z1 = z;
        } else if (v > s2 || (v == s2 && z < z2)) {
            s2 = v; z2 = z;
        }
    }
    int o = bl * 2;
    out[OFF_S  + o]     = s1;
    out[OFF_S  + o + 1] = s2;
    out[OFF_N  + o]     = (float)(z1 >> 2);
    out[OFF_N  + o + 1] = (float)(z2 >> 2);
    out[OFF_LK + o]     = (float)((z1 >> 1) & 1);
    out[OFF_LK + o + 1] = (float)((z2 >> 1) & 1);
    out[OFF_RK + o]     = (float)(z1 & 1);
    out[OFF_RK + o + 1] = (float)(z2 & 1);
    g_sel[o]     = make_int4(z1 >> 2, (z1 >> 1) & 1, z1 & 1, 0);
    g_sel[o + 1] = make_int4(z2 >> 2, (z2 >> 1) & 1, z2 & 1, 0);
}

// ---------------------------------------------------------------------------
// K6: split-K compose GEMM (unchanged from round 2).
__global__ __launch_bounds__(256, 2) void gemm2_kernel(
    const float* __restrict__ chart_h, const float* __restrict__ Wc) {
    __shared__ float As2[16][256];
    __shared__ float Bs[16][128];
    __shared__ const float* Arow[128];

    int tid  = threadIdx.x;
    int row0 = blockIdx.y * 128;
    int col0 = blockIdx.x * 128;
    int ks   = blockIdx.z;
    int kbase = ks * 256;

    if (tid < 128) {
        int r = row0 + tid;
        int bl = r >> 1;
        int b = bl / LPOS, l = bl % LPOS;
        int4 sel = g_sel[r];
        const float* base;
        if (kbase < 512) {
            int lcell = g_li[(l << 4) + sel.x];
            base = chart_h + (((size_t)(sel.y * BATCH + b)) * NCELLS + lcell) * SIZE + kbase;
        } else {
            int rcell = g_ri[(l << 4) + sel.x];
            base = chart_h + (((size_t)(sel.z * BATCH + b)) * NCELLS + rcell) * SIZE + (kbase - 512);
        }
        Arow[tid] = base;
    }
    __syncthreads();

    u64t acc[8][4];
#pragma unroll
    for (int i = 0; i < 8; i++)
#pragma unroll
        for (int j = 0; j < 4; j++) acc[i][j] = 0ull;

    int arow  = tid >> 1;
    int ahalf = (tid & 1) * 8;
    int brow  = tid >> 5;
    int bcol4 = (tid & 31) * 4;
    int ty = tid >> 4, tx = tid & 15;

    for (int kk = 0; kk < 256; kk += 16) {
        float4 av0 = *(const float4*)(Arow[arow] + kk + ahalf);
        float4 av1 = *(const float4*)(Arow[arow] + kk + ahalf + 4);
        *(float2*)&As2[ahalf + 0][2 * arow] = make_float2(av0.x, av0.x);
        *(float2*)&As2[ahalf + 1][2 * arow] = make_float2(av0.y, av0.y);
        *(float2*)&As2[ahalf + 2][2 * arow] = make_float2(av0.z, av0.z);
        *(float2*)&As2[ahalf + 3][2 * arow] = make_float2(av0.w, av0.w);
        *(float2*)&As2[ahalf + 4][2 * arow] = make_float2(av1.x, av1.x);
        *(float2*)&As2[ahalf + 5][2 * arow] = make_float2(av1.y, av1.y);
        *(float2*)&As2[ahalf + 6][2 * arow] = make_float2(av1.z, av1.z);
        *(float2*)&As2[ahalf + 7][2 * arow] = make_float2(av1.w, av1.w);
        int kg = kbase + kk;
        *(float4*)(&Bs[brow][bcol4]) =
            *(const float4*)(Wc + (size_t)(kg + brow) * 512 + col0 + bcol4);
        *(float4*)(&Bs[brow + 8][bcol4]) =
            *(const float4*)(Wc + (size_t)(kg + brow + 8) * 512 + col0 + bcol4);
        __syncthreads();
#pragma unroll
        for (int kq = 0; kq < 16; kq++) {
            u64t a2[8], b2[4];
#pragma unroll
            for (int i = 0; i < 8; i++)
                a2[i] = *(const u64t*)&As2[kq][2 * (ty * 8 + i)];
#pragma unroll
            for (int j = 0; j < 4; j++)
                b2[j] = ((const u64t*)&Bs[kq][tx * 8])[j];
#pragma unroll
            for (int i = 0; i < 8; i++)
#pragma unroll
                for (int j = 0; j < 4; j++) FFMA2(acc[i][j], a2[i], b2[j]);
        }
        __syncthreads();
    }
#pragma unroll
    for (int i = 0; i < 8; i++) {
        int r = row0 + ty * 8 + i;
        u64t* crow = (u64t*)(g_P + ((size_t)ks * ROWS2 + r) * 512 + col0 + tx * 8);
#pragma unroll
        for (int j = 0; j < 4; j++) crow[j] = acc[i][j];
    }
}

// ---------------------------------------------------------------------------
// K7: combine split-K partials + bias + tanh + unit-norm, write topk_h.
__global__ __launch_bounds__(256) void combine_normalize_kernel(
    const float* __restrict__ bc, float* __restrict__ out) {
    int r = blockIdx.x;
    int t = threadIdx.x;
    const float* p = g_P + (size_t)r * 512;
    const size_t stride = (size_t)ROWS2 * 512;

    float v0 = bc[t]       + p[t]       + p[t + stride]       + p[t + 2*stride]       + p[t + 3*stride];
    float v1 = bc[t + 256] + p[t + 256] + p[t + 256 + stride] + p[t + 256 + 2*stride] + p[t + 256 + 3*stride];
    v0 = tanhf(v0);
    v1 = tanhf(v1);

    float ss = v0 * v0 + v1 * v1;
#pragma unroll
    for (int o = 16; o; o >>= 1) ss += __shfl_xor_sync(0xffffffffu, ss, o);
    __shared__ float red[8];
    __shared__ float s_inv;
    if ((t & 31) == 0) red[t >> 5] = ss;
    __syncthreads();
    if (t == 0) {
        float x = 0.f;
#pragma unroll
        for (int i = 0; i < 8; i++) x += red[i];
        s_inv = 1.0f / sqrtf(x);
    }
    __syncthreads();
    float inv = s_inv;
    out[OFF_H + (size_t)r * 512 + t]       = v0 * inv;
    out[OFF_H + (size_t)r * 512 + t + 256] = v1 * inv;
}

// ---------------------------------------------------------------------------
extern "C" void kernel_launch(void* const* d_in, const int* in_sizes, int n_in,
                              void* d_out, int out_size) {
    const float* chart_h = (const float*)d_in[0];
    const float* chart_s = (const float*)d_in[1];
    const void*  l_index = d_in[2];
    const void*  r_index = d_in[3];
    const float* mat     = (const float*)d_in[4];
    const float* Wc      = (const float*)d_in[5];
    const float* bc      = (const float*)d_in[6];
    float* out = (float*)d_out;

    conv_idx_kernel<<<3, 256>>>(l_index, r_index);
    gemm1_tf32_kernel<<<dim3(4, ROWS1 / 128), 256>>>(chart_h, mat);
    score_approx_kernel<<<NCELLS_BL, 256>>>(chart_h, chart_s);
    rescore_gemm_kernel<<<dim3(4, MAXROWS / 128), 256>>>(chart_h, mat);
    rescore_dot_kernel<<<MAXROWS / 8, 256>>>(chart_h, chart_s);
    final_select_kernel<<<(NCELLS_BL + 255) / 256, 256>>>(out);
    gemm2_kernel<<<dim3(4, ROWS2 / 128, KSPLIT), 256>>>(chart_h, Wc);
    combine_normalize_kernel<<<ROWS2, 256>>>(bc, out);
}